// round 7
// baseline (speedup 1.0000x reference)
#include <cuda_runtime.h>
#include <cstdint>

#define IMG 128
#define BR  512
#define NSTROKES 1024
#define LSTROKES 256

// Scratch (device-global; no mallocs allowed).
__device__ uint32_t g_mask[2 * (BR * BR / 32)];   // fine brush>0 mask (fallback)
__device__ uint32_t g_coarse[512];                // 1 bit per fine word == all-ones
// SoA stroke params
__device__ float g_w00[NSTROKES], g_w01[NSTROKES], g_w02[NSTROKES];
__device__ float g_w10[NSTROKES], g_w11[NSTROKES], g_w12[NSTROKES];
__device__ float g_cr[NSTROKES], g_cg[NSTROKES], g_cb[NSTROKES];
__device__ int   g_bidx[NSTROKES];

// ---------------------------------------------------------------------------
// Kernel 1 (fused): blocks [0,64) build fine mask + coarse summary;
// blocks [64,96) compute stroke warp matrices (fp64 sin/cos over 32 SMs).
// ---------------------------------------------------------------------------
__global__ void prep_and_mask_kernel(const float* __restrict__ params,
                                     const float* __restrict__ brushes) {
    const int bid = blockIdx.x;
    const int t = threadIdx.x;

    if (bid < 64) {
        const int word = bid * 256 + t;                 // 0 .. 16383
        const float4* src = (const float4*)brushes + word * 8;
        uint32_t m = 0;
        #pragma unroll
        for (int j = 0; j < 8; ++j) {
            float4 v = src[j];
            m |= ((v.x > 0.0f) ? 1u : 0u) << (4 * j + 0);
            m |= ((v.y > 0.0f) ? 1u : 0u) << (4 * j + 1);
            m |= ((v.z > 0.0f) ? 1u : 0u) << (4 * j + 2);
            m |= ((v.w > 0.0f) ? 1u : 0u) << (4 * j + 3);
        }
        g_mask[word] = m;
        unsigned full = __ballot_sync(0xFFFFFFFFu, m == 0xFFFFFFFFu);
        if ((t & 31) == 0) g_coarse[word >> 5] = full;
    } else {
        if (t >= 32) return;
        const int n = (bid - 64) * 32 + t;              // 0 .. 1023
        const float* p = params + n * 8;
        float x0 = p[0], y0 = p[1], w = p[2], h = p[3], th = p[4];

        // JAX: sin(fl32(pi)*theta), f32 product; correctly-rounded double
        // sin/cos keeps binary-alpha decisions bit-stable vs reference.
        float prod = 3.14159274101257324219f * th;
        float s = (float)sin((double)prod);
        float c = (float)cos((double)prod);

        float tx = 1.0f - 2.0f * x0;
        float ty = 1.0f - 2.0f * y0;
        g_w00[n] = c / w;
        g_w01[n] = s / w;
        g_w02[n] = (tx * c) / w + (ty * s) / w;
        g_w10[n] = -(s / h);
        g_w11[n] = c / h;
        g_w12[n] = (ty * c) / h - (tx * s) / h;
        g_cr[n] = p[5]; g_cg[n] = p[6]; g_cb[n] = p[7];
        g_bidx[n] = (h > w) ? 0 : 1;
    }
}

// ---------------------------------------------------------------------------
// Render helpers
// ---------------------------------------------------------------------------
__device__ __forceinline__ bool alpha_slow(int brush, float gx, float gy) {
    float x = ((gx + 1.0f) * 512.0f - 1.0f) * 0.5f;
    float y = ((gy + 1.0f) * 512.0f - 1.0f) * 0.5f;
    int ix = __float2int_rn(x);
    int iy = __float2int_rn(y);
    if ((unsigned)ix >= 512u || (unsigned)iy >= 512u) return false;
    int wi = (brush << 13) + (iy << 4) + (ix >> 5);
    if ((__ldg(g_coarse + (wi >> 5)) >> (wi & 31)) & 1u) return true;
    return (__ldg(g_mask + wi) >> (ix & 31)) & 1u;
}

__device__ __forceinline__ bool valid_fast(float bxn, float byn,
                                           float w00, float w01, float w02,
                                           float w10, float w11, float w12) {
    // all-ones mask: eroded alpha point test == rounded sample in-bounds.
    // EXACT formulas (must match reference rounding bit-for-bit).
    const float gx = fmaf(bxn, w00, fmaf(byn, w01, w02));
    const float gy = fmaf(bxn, w10, fmaf(byn, w11, w12));
    const float x = ((gx + 1.0f) * 512.0f - 1.0f) * 0.5f;
    const float y = ((gy + 1.0f) * 512.0f - 1.0f) * 0.5f;
    const int ix = __float2int_rn(x);
    const int iy = __float2int_rn(y);
    return ((unsigned)ix < 512u) & ((unsigned)iy < 512u);
}

__device__ __forceinline__ float tap(const float* __restrict__ im, int ix, int iy) {
    bool valid = ((unsigned)ix < 512u) && ((unsigned)iy < 512u);
    int cx = min(max(ix, 0), 511);
    int cy = min(max(iy, 0), 511);
    float v = __ldg(im + cy * 512 + cx);
    return valid ? v : 0.0f;
}

__device__ __forceinline__ float bgrid(int i) {     // exact base-grid coord
    return (2.0f * (float)i + 1.0f) * (1.0f / 128.0f) - 1.0f;
}

// ---------------------------------------------------------------------------
// Render: block = 4 warps over ONE 8x4 tile. Warp k owns strokes l ≡ k (mod 4)
// descending. Per 32-stroke round: lane-parallel interval + tile-full-cover
// tests; highest full-cover stroke resolves ALL lanes in O(1); only partial
// candidates ABOVE it are processed per-pixel (params via shfl, predicated).
// ---------------------------------------------------------------------------
__global__ __launch_bounds__(128)
void render_kernel(const float* __restrict__ brushes, float* __restrict__ out) {
    __shared__ int s_win[4][32];

    const int t = threadIdx.x;
    const int warp = t >> 5, lane = t & 31;
    const int b = blockIdx.z;
    const int off = b * LSTROKES;

    // Block-uniform "every brush texel > 0" flag (common case: true).
    bool fullv = true;
    #pragma unroll
    for (int i = 0; i < 4; ++i) fullv &= (__ldg(g_coarse + t + 128 * i) == 0xFFFFFFFFu);
    const bool allones = __syncthreads_and(fullv ? 1 : 0) != 0;

    const int tileX = blockIdx.x * 8;
    const int tileY = blockIdx.y * 4;
    const int w = tileX + (lane & 7);
    const int h = tileY + (lane >> 3);
    const float bx = bgrid(w);
    const float by = bgrid(h);
    const float c64 = 0.015625f;                      // 1/64 grid step (exact)
    const float bxl = bx - ((w > 0)   ? c64 : 0.0f);
    const float bxh = bx + ((w < 127) ? c64 : 0.0f);
    const float byl = by - ((h > 0)   ? c64 : 0.0f);
    const float byh = by + ((h < 127) ? c64 : 0.0f);
    // Tile-wide expanded-stencil rect corners.
    const float tx0 = bgrid(max(tileX - 1, 0)), tx1 = bgrid(min(tileX + 8, 127));
    const float ty0 = bgrid(max(tileY - 1, 0)), ty1 = bgrid(min(tileY + 4, 127));
    // Interval-test tile extent.
    const float ix0 = bgrid(tileX), ix1 = bgrid(tileX + 7);
    const float iy0 = bgrid(tileY), iy1 = bgrid(tileY + 3);

    int myWin = -1;
    bool done = false;

    #pragma unroll 1
    for (int r = 0; r < 2 && !__all_sync(0xFFFFFFFFu, done); ++r) {
        // Lane's deck stroke (descending: lane 0 = highest).
        const int p = r * 32 + lane;
        const int sl = off + (63 - p) * 4 + warp;
        const float a  = __ldg(g_w00 + sl), bb = __ldg(g_w01 + sl), cc = __ldg(g_w02 + sl);
        const float d  = __ldg(g_w10 + sl), e  = __ldg(g_w11 + sl), f  = __ldg(g_w12 + sl);

        // Interval overlap (conservative reject).
        const float gxlo = cc + fminf(ix0 * a, ix1 * a) + fminf(iy0 * bb, iy1 * bb);
        const float gxhi = cc + fmaxf(ix0 * a, ix1 * a) + fmaxf(iy0 * bb, iy1 * bb);
        const float gylo = f  + fminf(ix0 * d, ix1 * d) + fminf(iy0 * e, iy1 * e);
        const float gyhi = f  + fmaxf(ix0 * d, ix1 * d) + fmaxf(iy0 * e, iy1 * e);
        const bool cand = (gxhi >= -1.002f) & (gxlo <= 1.002f) &
                          (gyhi >= -1.002f) & (gylo <= 1.002f);

        // Lane-parallel tile full-cover test (exact; warp-uniform per stroke).
        bool full = false;
        if (allones && cand) {
            full = valid_fast(tx0, ty0, a, bb, cc, d, e, f) &
                   valid_fast(tx0, ty1, a, bb, cc, d, e, f) &
                   valid_fast(tx1, ty0, a, bb, cc, d, e, f) &
                   valid_fast(tx1, ty1, a, bb, cc, d, e, f);
        }

        const unsigned candM = __ballot_sync(0xFFFFFFFFu, cand);
        const unsigned fullM = __ballot_sync(0xFFFFFFFFu, full);

        int fullLane = -1;
        unsigned procM = candM;
        if (fullM) {
            fullLane = __ffs(fullM) - 1;                 // highest full stroke
            procM = candM & ((1u << fullLane) - 1u);     // only partials above it
        }

        // Serial loop over remaining candidates (predicated, params via shfl).
        int iter = 0;
        while (procM) {
            const int bit = __ffs(procM) - 1;            // highest stroke first
            procM &= procM - 1;
            const float w00 = __shfl_sync(0xFFFFFFFFu, a,  bit);
            const float w01 = __shfl_sync(0xFFFFFFFFu, bb, bit);
            const float w02 = __shfl_sync(0xFFFFFFFFu, cc, bit);
            const float w10 = __shfl_sync(0xFFFFFFFFu, d,  bit);
            const float w11 = __shfl_sync(0xFFFFFFFFu, e,  bit);
            const float w12 = __shfl_sync(0xFFFFFFFFu, f,  bit);
            const int l = (63 - (r * 32 + bit)) * 4 + warp;

            if (!done) {
                if (allones) {
                    const bool ok =
                        valid_fast(bxl, byl, w00, w01, w02, w10, w11, w12) &
                        valid_fast(bxl, byh, w00, w01, w02, w10, w11, w12) &
                        valid_fast(bxh, byl, w00, w01, w02, w10, w11, w12) &
                        valid_fast(bxh, byh, w00, w01, w02, w10, w11, w12);
                    if (ok) { myWin = l; done = true; }
                } else {
                    const int idx = __ldg(g_bidx + off + l);
                    const float gx = fmaf(bx, w00, fmaf(by, w01, w02));
                    const float gy = fmaf(bx, w10, fmaf(by, w11, w12));
                    if (alpha_slow(idx, gx, gy)) {
                        bool ok = true;
                        #pragma unroll
                        for (int k = 0; k < 9; ++k) {
                            const int dh = k / 3 - 1, dw = k % 3 - 1;
                            if (dh == 0 && dw == 0) continue;
                            if ((unsigned)(h + dh) >= 128u) continue;
                            if ((unsigned)(w + dw) >= 128u) continue;
                            const float bxn = bx + (float)dw * c64;
                            const float byn = by + (float)dh * c64;
                            const float gxn = fmaf(bxn, w00, fmaf(byn, w01, w02));
                            const float gyn = fmaf(bxn, w10, fmaf(byn, w11, w12));
                            ok &= alpha_slow(idx, gxn, gyn);
                        }
                        if (ok) { myWin = l; done = true; }
                    }
                }
            }
            if ((++iter & 7) == 0 && __all_sync(0xFFFFFFFFu, done)) break;
        }

        // Resolve all still-open lanes to the highest full-cover stroke.
        if (fullLane >= 0) {
            if (!done) {
                myWin = (63 - (r * 32 + fullLane)) * 4 + warp;
                done = true;
            }
        }
    }

    s_win[warp][lane] = myWin;
    __syncthreads();

    // Warp 0: combine deck winners by max, bilinear-sample, write.
    if (warp == 0) {
        const int wn = max(max(s_win[0][lane], s_win[1][lane]),
                           max(s_win[2][lane], s_win[3][lane]));
        float oR = 0.0f, oG = 0.0f, oB = 0.0f;
        if (wn >= 0) {
            const int gl = off + wn;
            const float w00 = __ldg(g_w00 + gl), w01 = __ldg(g_w01 + gl), w02 = __ldg(g_w02 + gl);
            const float w10 = __ldg(g_w10 + gl), w11 = __ldg(g_w11 + gl), w12 = __ldg(g_w12 + gl);
            const int   idx = __ldg(g_bidx + gl);
            const float gx = fmaf(bx, w00, fmaf(by, w01, w02));
            const float gy = fmaf(bx, w10, fmaf(by, w11, w12));
            const float* im = brushes + (size_t)idx * (BR * BR);
            const float x = ((gx + 1.0f) * 512.0f - 1.0f) * 0.5f;
            const float y = ((gy + 1.0f) * 512.0f - 1.0f) * 0.5f;
            const float xf = floorf(x), yf = floorf(y);
            const int x0i = (int)xf, y0i = (int)yf;
            const float wx1 = x - xf, wx0 = 1.0f - wx1;
            const float wy1 = y - yf, wy0 = 1.0f - wy1;
            const float sV =
                tap(im, x0i,     y0i)     * (wx0 * wy0) +
                tap(im, x0i + 1, y0i)     * (wx1 * wy0) +
                tap(im, x0i,     y0i + 1) * (wx0 * wy1) +
                tap(im, x0i + 1, y0i + 1) * (wx1 * wy1);
            oR = sV * __ldg(g_cr + gl);
            oG = sV * __ldg(g_cg + gl);
            oB = sV * __ldg(g_cb + gl);
        }
        const int outb = ((b * 3) * IMG + h) * IMG + w;
        out[outb]                 = oR;
        out[outb + IMG * IMG]     = oG;
        out[outb + 2 * IMG * IMG] = oB;
    }
}

// ---------------------------------------------------------------------------
extern "C" void kernel_launch(void* const* d_in, const int* in_sizes, int n_in,
                              void* d_out, int out_size) {
    const float* params  = (const float*)d_in[0];   // (4,256,8)
    const float* brushes = (const float*)d_in[1];   // (2,1,512,512)
    float* out = (float*)d_out;                     // (4,3,128,128)

    (void)in_sizes; (void)n_in; (void)out_size;

    prep_and_mask_kernel<<<96, 256>>>(params, brushes);

    dim3 grid(IMG / 8, IMG / 4, 4);                 // 2048 blocks x 128 threads
    render_kernel<<<grid, 128>>>(brushes, out);
}

// round 8
// speedup vs baseline: 1.0201x; 1.0201x over previous
#include <cuda_runtime.h>
#include <cstdint>

#define IMG 128
#define BR  512
#define NSTROKES 1024
#define LSTROKES 256

// Scratch (device-global; no mallocs allowed).
__device__ uint32_t g_mask[2 * (BR * BR / 32)];   // fine brush>0 mask (fallback)
__device__ uint32_t g_coarse[512];                // 1 bit per fine word == all-ones
__device__ int      g_blockfull[64];              // per-prep-block "all ones" flag
// SoA stroke params
__device__ float g_w00[NSTROKES], g_w01[NSTROKES], g_w02[NSTROKES];
__device__ float g_w10[NSTROKES], g_w11[NSTROKES], g_w12[NSTROKES];
__device__ float g_cr[NSTROKES], g_cg[NSTROKES], g_cb[NSTROKES];
__device__ int   g_bidx[NSTROKES];

// ---------------------------------------------------------------------------
// Kernel 1 (fused): blocks [0,64) build fine mask + coarse summary + block
// all-ones flag; blocks [64,96) compute stroke warp matrices (fp64 sin/cos
// spread over 32 SMs).
// ---------------------------------------------------------------------------
__global__ void prep_and_mask_kernel(const float* __restrict__ params,
                                     const float* __restrict__ brushes) {
    const int bid = blockIdx.x;
    const int t = threadIdx.x;

    if (bid < 64) {
        __shared__ uint32_t s_f[8];
        const int word = bid * 256 + t;                 // 0 .. 16383
        const float4* src = (const float4*)brushes + word * 8;
        uint32_t m = 0;
        #pragma unroll
        for (int j = 0; j < 8; ++j) {
            float4 v = src[j];
            m |= ((v.x > 0.0f) ? 1u : 0u) << (4 * j + 0);
            m |= ((v.y > 0.0f) ? 1u : 0u) << (4 * j + 1);
            m |= ((v.z > 0.0f) ? 1u : 0u) << (4 * j + 2);
            m |= ((v.w > 0.0f) ? 1u : 0u) << (4 * j + 3);
        }
        g_mask[word] = m;
        unsigned full = __ballot_sync(0xFFFFFFFFu, m == 0xFFFFFFFFu);
        if ((t & 31) == 0) { g_coarse[word >> 5] = full; s_f[t >> 5] = full; }
        __syncthreads();
        if (t == 0) {
            bool all = true;
            #pragma unroll
            for (int i = 0; i < 8; ++i) all &= (s_f[i] == 0xFFFFFFFFu);
            g_blockfull[bid] = all ? 1 : 0;
        }
    } else {
        if (t >= 32) return;
        const int n = (bid - 64) * 32 + t;              // 0 .. 1023
        const float* p = params + n * 8;
        float x0 = p[0], y0 = p[1], w = p[2], h = p[3], th = p[4];

        // JAX: sin(fl32(pi)*theta), f32 product; correctly-rounded double
        // sin/cos keeps binary-alpha decisions bit-stable vs reference.
        float prod = 3.14159274101257324219f * th;
        float s = (float)sin((double)prod);
        float c = (float)cos((double)prod);

        float tx = 1.0f - 2.0f * x0;
        float ty = 1.0f - 2.0f * y0;
        g_w00[n] = c / w;
        g_w01[n] = s / w;
        g_w02[n] = (tx * c) / w + (ty * s) / w;
        g_w10[n] = -(s / h);
        g_w11[n] = c / h;
        g_w12[n] = (ty * c) / h - (tx * s) / h;
        g_cr[n] = p[5]; g_cg[n] = p[6]; g_cb[n] = p[7];
        g_bidx[n] = (h > w) ? 0 : 1;
    }
}

// ---------------------------------------------------------------------------
// Render helpers (EXACT formulas — must match reference bit-for-bit).
// ---------------------------------------------------------------------------
__device__ __forceinline__ bool alpha_slow(int brush, float gx, float gy) {
    float x = ((gx + 1.0f) * 512.0f - 1.0f) * 0.5f;
    float y = ((gy + 1.0f) * 512.0f - 1.0f) * 0.5f;
    int ix = __float2int_rn(x);
    int iy = __float2int_rn(y);
    if ((unsigned)ix >= 512u || (unsigned)iy >= 512u) return false;
    int wi = (brush << 13) + (iy << 4) + (ix >> 5);
    if ((__ldg(g_coarse + (wi >> 5)) >> (wi & 31)) & 1u) return true;
    return (__ldg(g_mask + wi) >> (ix & 31)) & 1u;
}

__device__ __forceinline__ bool valid_fast(float bxn, float byn,
                                           float w00, float w01, float w02,
                                           float w10, float w11, float w12) {
    const float gx = fmaf(bxn, w00, fmaf(byn, w01, w02));
    const float gy = fmaf(bxn, w10, fmaf(byn, w11, w12));
    const float x = ((gx + 1.0f) * 512.0f - 1.0f) * 0.5f;
    const float y = ((gy + 1.0f) * 512.0f - 1.0f) * 0.5f;
    const int ix = __float2int_rn(x);
    const int iy = __float2int_rn(y);
    return ((unsigned)ix < 512u) & ((unsigned)iy < 512u);
}

__device__ __forceinline__ float tap(const float* __restrict__ im, int ix, int iy) {
    bool valid = ((unsigned)ix < 512u) && ((unsigned)iy < 512u);
    int cx = min(max(ix, 0), 511);
    int cy = min(max(iy, 0), 511);
    float v = __ldg(im + cy * 512 + cx);
    return valid ? v : 0.0f;
}

__device__ __forceinline__ float bgrid(int i) {     // exact base-grid coord
    return (2.0f * (float)i + 1.0f) * (1.0f / 128.0f) - 1.0f;
}

// ---------------------------------------------------------------------------
// Render: block = 4 warps over ONE 8x4 tile; warp k owns strokes l ≡ k (mod 4)
// descending. Candidate + full-cover both from ONE center±deviation interval
// test (exact interval arithmetic with conservative thresholds); exact paths
// only for the rare boundary candidates.
// ---------------------------------------------------------------------------
__global__ __launch_bounds__(128)
void render_kernel(const float* __restrict__ brushes, float* __restrict__ out) {
    __shared__ int s_win[4][32];

    const int t = threadIdx.x;
    const int warp = t >> 5, lane = t & 31;
    const int b = blockIdx.z;
    const int off = b * LSTROKES;

    // Block-uniform "every brush texel > 0" flag from 64 precomputed flags.
    bool fv = true;
    if (t < 64) fv = (__ldg(g_blockfull + t) != 0);
    const bool allones = __syncthreads_and(fv ? 1 : 0) != 0;

    const int tileX = blockIdx.x * 8;
    const int tileY = blockIdx.y * 4;
    const int w = tileX + (lane & 7);
    const int h = tileY + (lane >> 3);
    const float bx = bgrid(w);
    const float by = bgrid(h);
    const float c64 = 0.015625f;
    const float bxl = bx - ((w > 0)   ? c64 : 0.0f);
    const float bxh = bx + ((w < 127) ? c64 : 0.0f);
    const float byl = by - ((h > 0)   ? c64 : 0.0f);
    const float byh = by + ((h < 127) ? c64 : 0.0f);
    // Expanded rect (tile ∪ erosion ring), center + half-extents.
    const float tx0 = bgrid(max(tileX - 1, 0)), tx1 = bgrid(min(tileX + 8, 127));
    const float ty0 = bgrid(max(tileY - 1, 0)), ty1 = bgrid(min(tileY + 4, 127));
    const float ecx = 0.5f * (tx0 + tx1), ehx = 0.5f * (tx1 - tx0);
    const float ecy = 0.5f * (ty0 + ty1), ehy = 0.5f * (ty1 - ty0);

    int myWin = -1;
    bool done = false;

    #pragma unroll 1
    for (int r = 0; r < 2 && !__all_sync(0xFFFFFFFFu, done); ++r) {
        // Lane's deck stroke (descending: lane 0 = highest).
        const int p = r * 32 + lane;
        const int sl = off + (63 - p) * 4 + warp;
        const float a  = __ldg(g_w00 + sl), bb = __ldg(g_w01 + sl), cc = __ldg(g_w02 + sl);
        const float d  = __ldg(g_w10 + sl), e  = __ldg(g_w11 + sl), f  = __ldg(g_w12 + sl);

        // Interval arithmetic over the expanded rect:
        //   |gx| over rect ∈ [ |gxc|-devx , |gxc|+devx ]
        const float gxc = fmaf(ecx, a, fmaf(ecy, bb, cc));
        const float gyc = fmaf(ecx, d, fmaf(ecy, e,  f));
        const float devx = fmaf(fabsf(a), ehx, fabsf(bb) * ehy);
        const float devy = fmaf(fabsf(d), ehx, fabsf(e)  * ehy);
        const float axc = fabsf(gxc), ayc = fabsf(gyc);

        const bool cand = (axc - devx <= 1.002f) & (ayc - devy <= 1.002f);
        const bool full = allones & cand &
                          (axc + devx <= 0.998f) & (ayc + devy <= 0.998f);

        const unsigned candM = __ballot_sync(0xFFFFFFFFu, cand);
        const unsigned fullM = __ballot_sync(0xFFFFFFFFu, full);

        int fullLane = -1;
        unsigned procM = candM;
        if (fullM) {
            fullLane = __ffs(fullM) - 1;                 // highest full stroke
            procM = candM & ((1u << fullLane) - 1u);     // only partials above it
        }

        // Serial loop over remaining candidates (predicated, params via shfl).
        int iter = 0;
        while (procM) {
            const int bit = __ffs(procM) - 1;            // highest stroke first
            procM &= procM - 1;
            const float w00 = __shfl_sync(0xFFFFFFFFu, a,  bit);
            const float w01 = __shfl_sync(0xFFFFFFFFu, bb, bit);
            const float w02 = __shfl_sync(0xFFFFFFFFu, cc, bit);
            const float w10 = __shfl_sync(0xFFFFFFFFu, d,  bit);
            const float w11 = __shfl_sync(0xFFFFFFFFu, e,  bit);
            const float w12 = __shfl_sync(0xFFFFFFFFu, f,  bit);
            const int l = (63 - (r * 32 + bit)) * 4 + warp;

            if (!done) {
                if (allones) {
                    // Exact per-pixel test: 4 clipped-stencil corners
                    // (monotone in each coordinate => corners suffice).
                    const bool ok =
                        valid_fast(bxl, byl, w00, w01, w02, w10, w11, w12) &
                        valid_fast(bxl, byh, w00, w01, w02, w10, w11, w12) &
                        valid_fast(bxh, byl, w00, w01, w02, w10, w11, w12) &
                        valid_fast(bxh, byh, w00, w01, w02, w10, w11, w12);
                    if (ok) { myWin = l; done = true; }
                } else {
                    const int idx = __ldg(g_bidx + off + l);
                    const float gx = fmaf(bx, w00, fmaf(by, w01, w02));
                    const float gy = fmaf(bx, w10, fmaf(by, w11, w12));
                    if (alpha_slow(idx, gx, gy)) {
                        bool ok = true;
                        #pragma unroll
                        for (int k = 0; k < 9; ++k) {
                            const int dh = k / 3 - 1, dw = k % 3 - 1;
                            if (dh == 0 && dw == 0) continue;
                            if ((unsigned)(h + dh) >= 128u) continue;
                            if ((unsigned)(w + dw) >= 128u) continue;
                            const float bxn = bx + (float)dw * c64;
                            const float byn = by + (float)dh * c64;
                            const float gxn = fmaf(bxn, w00, fmaf(byn, w01, w02));
                            const float gyn = fmaf(bxn, w10, fmaf(byn, w11, w12));
                            ok &= alpha_slow(idx, gxn, gyn);
                        }
                        if (ok) { myWin = l; done = true; }
                    }
                }
            }
            if ((++iter & 7) == 0 && __all_sync(0xFFFFFFFFu, done)) break;
        }

        // Resolve all still-open lanes to the highest full-cover stroke.
        if (fullLane >= 0 && !done) {
            myWin = (63 - (r * 32 + fullLane)) * 4 + warp;
            done = true;
        }
    }

    s_win[warp][lane] = myWin;
    __syncthreads();

    // Warp 0: combine deck winners by max, bilinear-sample, write.
    if (warp == 0) {
        const int wn = max(max(s_win[0][lane], s_win[1][lane]),
                           max(s_win[2][lane], s_win[3][lane]));
        float oR = 0.0f, oG = 0.0f, oB = 0.0f;
        if (wn >= 0) {
            const int gl = off + wn;
            const float w00 = __ldg(g_w00 + gl), w01 = __ldg(g_w01 + gl), w02 = __ldg(g_w02 + gl);
            const float w10 = __ldg(g_w10 + gl), w11 = __ldg(g_w11 + gl), w12 = __ldg(g_w12 + gl);
            const int   idx = __ldg(g_bidx + gl);
            const float gx = fmaf(bx, w00, fmaf(by, w01, w02));
            const float gy = fmaf(bx, w10, fmaf(by, w11, w12));
            const float* im = brushes + (size_t)idx * (BR * BR);
            const float x = ((gx + 1.0f) * 512.0f - 1.0f) * 0.5f;
            const float y = ((gy + 1.0f) * 512.0f - 1.0f) * 0.5f;
            const float xf = floorf(x), yf = floorf(y);
            const int x0i = (int)xf, y0i = (int)yf;
            const float wx1 = x - xf, wx0 = 1.0f - wx1;
            const float wy1 = y - yf, wy0 = 1.0f - wy1;
            const float sV =
                tap(im, x0i,     y0i)     * (wx0 * wy0) +
                tap(im, x0i + 1, y0i)     * (wx1 * wy0) +
                tap(im, x0i,     y0i + 1) * (wx0 * wy1) +
                tap(im, x0i + 1, y0i + 1) * (wx1 * wy1);
            oR = sV * __ldg(g_cr + gl);
            oG = sV * __ldg(g_cg + gl);
            oB = sV * __ldg(g_cb + gl);
        }
        const int outb = ((b * 3) * IMG + h) * IMG + w;
        out[outb]                 = oR;
        out[outb + IMG * IMG]     = oG;
        out[outb + 2 * IMG * IMG] = oB;
    }
}

// ---------------------------------------------------------------------------
extern "C" void kernel_launch(void* const* d_in, const int* in_sizes, int n_in,
                              void* d_out, int out_size) {
    const float* params  = (const float*)d_in[0];   // (4,256,8)
    const float* brushes = (const float*)d_in[1];   // (2,1,512,512)
    float* out = (float*)d_out;                     // (4,3,128,128)

    (void)in_sizes; (void)n_in; (void)out_size;

    prep_and_mask_kernel<<<96, 256>>>(params, brushes);

    dim3 grid(IMG / 8, IMG / 4, 4);                 // 2048 blocks x 128 threads
    render_kernel<<<grid, 128>>>(brushes, out);
}